// round 15
// baseline (speedup 1.0000x reference)
#include <cuda_runtime.h>
#include <cuda_fp16.h>
#include <cstdint>

#define BDIM 2048
#define TDIM 128
#define FDIM 64
#define HDIM 256
#define OUTL 32
#define FCH  256

#define ROWS 16
#define RP   8
#define NTHR 256
#define NCTA (BDIM / ROWS)   // 128
#define PAD  18

typedef unsigned long long u64;
typedef unsigned int u32;

// ---------------- scratch (__device__ globals; no allocations) ----------------
__device__ __half g_hsh[(size_t)BDIM * TDIM * HDIM];     // 128 MB fp16 hs [b][t][h]
__device__ float  g_gi[(size_t)BDIM * TDIM * 768];       // 805 MB fp32 gi [ec][t][r16][768]
__device__ float  g_A[BDIM * TDIM];
__device__ float  g_C[BDIM * TDIM];
__device__ float4 g_W4[256 * 256];     // encoder Whh [k][j]: (wr, wz, wn, 0)
__device__ float4 g_Wx4[64 * 256];     // encoder Wih [f][j]: (wr, wz, wn, 0)
__device__ float2 g_DWrz[256 * 256];   // decoder Whh [k][j]
__device__ float  g_DWn [256 * 256];
__device__ float  g_WtFc1[HDIM * FCH]; // [k][j]

// ---------------- scalar helpers ----------------
__device__ __forceinline__ u64 pk2(float v) {
    u64 r; u32 u = __float_as_uint(v);
    asm("mov.b64 %0, {%1, %2};" : "=l"(r) : "r"(u), "r"(u));
    return r;
}
__device__ __forceinline__ u64 pk2p(float a, float b) {
    u64 r;
    asm("mov.b64 %0, {%1, %2};" : "=l"(r)
        : "r"(__float_as_uint(a)), "r"(__float_as_uint(b)));
    return r;
}
__device__ __forceinline__ float2 upk(u64 v) {
    u32 lo, hi;
    asm("mov.b64 {%0, %1}, %2;" : "=r"(lo), "=r"(hi) : "l"(v));
    return make_float2(__uint_as_float(lo), __uint_as_float(hi));
}
__device__ __forceinline__ void fma2(u64& acc, u64 a, u64 b) {
    asm("fma.rn.f32x2 %0, %1, %2, %0;" : "+l"(acc) : "l"(a), "l"(b));
}
__device__ __forceinline__ u64 lds2(const float* p) {
    return *reinterpret_cast<const u64*>(p);
}
__device__ __forceinline__ float sigmoidf_(float x) {
    float e = __expf(-x);
    return __fdividef(1.0f, 1.0f + e);
}
__device__ __forceinline__ float tanhf_(float x) {
    float xx = fminf(fmaxf(x, -15.f), 15.f);
    float e = __expf(2.f * xx);
    return __fdividef(e - 1.f, e + 1.f);
}
__device__ __forceinline__ u32 smem_u32(const void* p) {
    u32 a;
    asm("{ .reg .u64 t; cvta.to.shared.u64 t, %1; cvt.u32.u64 %0, t; }" : "=r"(a) : "l"(p));
    return a;
}
__device__ __forceinline__ void cp16(u32 dst, const void* src) {
    asm volatile("cp.async.ca.shared.global [%0], [%1], 16;" :: "r"(dst), "l"(src) : "memory");
}
#define CP_COMMIT() asm volatile("cp.async.commit_group;" ::: "memory")
#define CP_WAIT0()  asm volatile("cp.async.wait_group 0;" ::: "memory")

// ---------------- prep: weight repack ----------------
__global__ void prep_kernel(const float* __restrict__ encWih,
                            const float* __restrict__ encWhh,
                            const float* __restrict__ decWhh,
                            const float* __restrict__ fc1W) {
    int i = blockIdx.x * blockDim.x + threadIdx.x;
    if (i < 64 * 256) {
        int f = i >> 8, j = i & 255;
        g_Wx4[i] = make_float4(encWih[j * FDIM + f],
                               encWih[(j + HDIM) * FDIM + f],
                               encWih[(j + 2 * HDIM) * FDIM + f], 0.f);
    }
    if (i < 256 * 256) {
        int k = i >> 8, j = i & 255;
        g_W4[i] = make_float4(encWhh[j * HDIM + k],
                              encWhh[(j + HDIM) * HDIM + k],
                              encWhh[(j + 2 * HDIM) * HDIM + k], 0.f);
        g_DWrz[i] = make_float2(decWhh[j * HDIM + k], decWhh[(j + HDIM) * HDIM + k]);
        g_DWn[i]  = decWhh[(j + 2 * HDIM) * HDIM + k];
        g_WtFc1[k * FCH + j] = fc1W[j * HDIM + k];
    }
}

// ---------------- gi precompute: gi[b,t,:] = x[b,t,:] @ Wih^T (fp32, parallel) ----------------
// one CTA per (ec, t): 16 rows x 768 outputs. Thread tid = hidden j; gates via float4.
__global__ void __launch_bounds__(NTHR)
gi_kernel(const float* __restrict__ x) {
    __shared__ float sx[FDIM * PAD];   // [f][r16]
    const int tid = threadIdx.x;
    const int ec = blockIdx.x >> 7;
    const int t  = blockIdx.x & 127;

    for (int i = tid; i < ROWS * FDIM; i += NTHR) {
        int r = i >> 6, f = i & 63;
        sx[f * PAD + r] = x[((size_t)(ec * ROWS + r) * TDIM + t) * FDIM + f];
    }
    __syncthreads();

    u64 ar[RP], az[RP], an[RP];
    u64 z0 = pk2(0.f);
    #pragma unroll
    for (int rp = 0; rp < RP; ++rp) { ar[rp] = z0; az[rp] = z0; an[rp] = z0; }

    #pragma unroll 4
    for (int f = 0; f < FDIM; ++f) {
        float4 w = g_Wx4[f * 256 + tid];
        u64 wr2 = pk2(w.x), wz2 = pk2(w.y), wn2 = pk2(w.z);
        #pragma unroll
        for (int rp = 0; rp < RP; ++rp) {
            u64 v = lds2(&sx[f * PAD + 2 * rp]);
            fma2(ar[rp], v, wr2);
            fma2(az[rp], v, wz2);
            fma2(an[rp], v, wn2);
        }
    }

    float* op = g_gi + ((size_t)(ec * TDIM + t) * ROWS) * 768;
    #pragma unroll
    for (int rp = 0; rp < RP; ++rp) {
        float2 vr = upk(ar[rp]), vz = upk(az[rp]), vn = upk(an[rp]);
        op[(2*rp)     * 768 + tid]       = vr.x;
        op[(2*rp + 1) * 768 + tid]       = vr.y;
        op[(2*rp)     * 768 + 256 + tid] = vz.x;
        op[(2*rp + 1) * 768 + 256 + tid] = vz.y;
        op[(2*rp)     * 768 + 512 + tid] = vn.x;
        op[(2*rp + 1) * 768 + 512 + tid] = vn.y;
    }
}

// ---------------- encoder: 512 threads, h-recurrence only, gi via cp.async (fp32) ----------------
// smem float offsets
#define E_H    0                     // 256*PAD = 4608
#define E_PART 4608                  // 256*49  = 12544
#define E_AC   17152                 // 256
#define E_GI   17408                 // 16*768 = 12288 floats (single buffer)
#define ENC_SMEM_FLOATS 29696        // 118784 bytes

__global__ void __launch_bounds__(512, 1)
encoder_kernel(const float* __restrict__ h0,
               const float* __restrict__ bih, const float* __restrict__ bhh,
               const float* __restrict__ attnWq, const float* __restrict__ attnBq) {
    extern __shared__ float sm[];
    float* sh_h    = sm + E_H;
    float* sh_part = sm + E_PART;
    float* sh_ac   = sm + E_AC;
    const float* gi_sm = sm + E_GI;
    const u32 gi_smb = smem_u32(sm + E_GI);

    const int t  = threadIdx.x;
    const int g  = t >> 8;
    const int tj = t & 255;
    const int wp = tj >> 5;
    const int row0 = blockIdx.x * ROWS;

    const float bias_r  = bih[tj]            + bhh[tj];
    const float bias_z  = bih[tj + HDIM]     + bhh[tj + HDIM];
    const float bias_in = bih[tj + 2 * HDIM];
    const float bias_hn = bhh[tj + 2 * HDIM];
    const float wqv = attnWq[tj];
    const float bqv = attnBq[tj];

    for (int i = t; i < ROWS * HDIM; i += 512) {
        int r = i >> 8, k = i & 255;
        sh_h[k * PAD + r] = h0[(size_t)(row0 + r) * HDIM + k];
    }
    // prologue: issue gi(step 0) copies
    const char* gi_src = reinterpret_cast<const char*>(g_gi)
                       + (size_t)blockIdx.x * TDIM * 49152;
    #pragma unroll
    for (int i = 0; i < 6; ++i) {
        int idx = t + 512 * i;
        cp16(gi_smb + idx * 16, gi_src + idx * 16);
    }
    CP_COMMIT();
    __syncthreads();

    const float4* __restrict__ W4 = g_W4;

    for (int step = 0; step < TDIM; ++step) {
        CP_WAIT0();                         // this thread's gi(step) copies landed

        u64 ar[RP], az[RP], an2[RP];
        if (g == 0) {
            u64 br2 = pk2(bias_r), bz2 = pk2(bias_z), bh2 = pk2(bias_hn);
            #pragma unroll
            for (int rp = 0; rp < RP; ++rp) { ar[rp]=br2; az[rp]=bz2; an2[rp]=bh2; }
            #pragma unroll 4
            for (int k = 0; k < 128; ++k) {
                float4 w = W4[k * 256 + tj];
                u64 wr2 = pk2(w.x), wz2 = pk2(w.y), wn2 = pk2(w.z);
                #pragma unroll
                for (int rp = 0; rp < RP; ++rp) {
                    u64 v = lds2(&sh_h[k * PAD + 2 * rp]);
                    fma2(ar[rp],  v, wr2);
                    fma2(az[rp],  v, wz2);
                    fma2(an2[rp], v, wn2);
                }
            }
        } else {
            u64 z0 = pk2(0.f);
            #pragma unroll
            for (int rp = 0; rp < RP; ++rp) { ar[rp]=z0; az[rp]=z0; an2[rp]=z0; }
            #pragma unroll 4
            for (int k = 128; k < 256; ++k) {
                float4 w = W4[k * 256 + tj];
                u64 wr2 = pk2(w.x), wz2 = pk2(w.y), wn2 = pk2(w.z);
                #pragma unroll
                for (int rp = 0; rp < RP; ++rp) {
                    u64 v = lds2(&sh_h[k * PAD + 2 * rp]);
                    fma2(ar[rp],  v, wr2);
                    fma2(az[rp],  v, wz2);
                    fma2(an2[rp], v, wn2);
                }
            }
            float* pp = sh_part + tj * 49;
            #pragma unroll
            for (int rp = 0; rp < RP; ++rp) {
                float2 v = upk(ar[rp]);  pp[2*rp]      = v.x; pp[2*rp + 1]      = v.y;
                float2 w = upk(az[rp]);  pp[16 + 2*rp] = w.x; pp[16 + 2*rp + 1] = w.y;
                float2 h = upk(an2[rp]); pp[32 + 2*rp] = h.x; pp[32 + 2*rp + 1] = h.y;
            }
        }
        __syncthreads();   // partials published; all threads' gi copies landed before this

        if (g == 0) {
            const float* pp = sh_part + tj * 49;
            float hnew[ROWS];
            #pragma unroll
            for (int rp = 0; rp < RP; ++rp) {
                float gr0 = gi_sm[(2*rp) * 768 + tj];
                float gr1 = gi_sm[(2*rp+1) * 768 + tj];
                float gz0 = gi_sm[(2*rp) * 768 + 256 + tj];
                float gz1 = gi_sm[(2*rp+1) * 768 + 256 + tj];
                float gn0 = gi_sm[(2*rp) * 768 + 512 + tj];
                float gn1 = gi_sm[(2*rp+1) * 768 + 512 + tj];
                float2 vr = upk(ar[rp]);  vr.x += pp[2*rp] + gr0;      vr.y += pp[2*rp + 1] + gr1;
                float2 vz = upk(az[rp]);  vz.x += pp[16 + 2*rp] + gz0; vz.y += pp[16 + 2*rp + 1] + gz1;
                float2 vh = upk(an2[rp]); vh.x += pp[32 + 2*rp];       vh.y += pp[32 + 2*rp + 1];
                float r0 = sigmoidf_(vr.x), r1 = sigmoidf_(vr.y);
                float z0 = sigmoidf_(vz.x), z1 = sigmoidf_(vz.y);
                float n0 = tanhf_(bias_in + gn0 + r0 * vh.x);
                float n1 = tanhf_(bias_in + gn1 + r1 * vh.y);
                float o0 = sh_h[tj * PAD + 2 * rp];
                float o1 = sh_h[tj * PAD + 2 * rp + 1];
                hnew[2*rp]     = (1.f - z0) * n0 + z0 * o0;
                hnew[2*rp + 1] = (1.f - z1) * n1 + z1 * o1;
            }
            size_t base = ((size_t)row0 * TDIM + step) * HDIM + tj;
            #pragma unroll
            for (int r = 0; r < ROWS; ++r) {
                sh_h[tj * PAD + r] = hnew[r];
                g_hsh[base + (size_t)r * TDIM * HDIM] = __float2half_rn(hnew[r]);
            }
            float pa[ROWS], pc[ROWS];
            #pragma unroll
            for (int r = 0; r < ROWS; ++r) { pa[r] = hnew[r] * wqv; pc[r] = hnew[r] * bqv; }
            #pragma unroll
            for (int off = 16; off; off >>= 1) {
                #pragma unroll
                for (int r = 0; r < ROWS; ++r) {
                    pa[r] += __shfl_xor_sync(0xffffffffu, pa[r], off);
                    pc[r] += __shfl_xor_sync(0xffffffffu, pc[r], off);
                }
            }
            if ((tj & 31) == 0) {
                #pragma unroll
                for (int r = 0; r < ROWS; ++r) {
                    sh_ac[wp * 32 + r * 2]     = pa[r];
                    sh_ac[wp * 32 + r * 2 + 1] = pc[r];
                }
            }
        }
        __syncthreads();   // gi reads done chip-wide; safe to overwrite buffer
        if (t < 32) {
            int r = t >> 1, isC = t & 1;
            float s = 0.f;
            #pragma unroll
            for (int w = 0; w < 8; ++w) s += sh_ac[w * 32 + r * 2 + isC];
            if (isC) g_C[(row0 + r) * TDIM + step] = s;
            else     g_A[(row0 + r) * TDIM + step] = s;
        }
        if (step + 1 < TDIM) {
            const char* src = gi_src + (size_t)(step + 1) * 49152;
            #pragma unroll
            for (int i = 0; i < 6; ++i) {
                int idx = t + 512 * i;
                cp16(gi_smb + idx * 16, src + idx * 16);
            }
        }
        CP_COMMIT();
    }
}

// ---------------- decoder: 512 threads, split-K, fp16 hs for ctx (unchanged) ----------------
#define D_CTX  0
#define D_A    4608
#define D_C    6656
#define D_W    8704
#define D_PART 10752
#define D_PREV 23040
#define D_RED  23056
#define DEC_SMEM_FLOATS 23312

__global__ void __launch_bounds__(512, 1)
decoder_kernel(const float* __restrict__ x,
               const float* __restrict__ dWih, const float* __restrict__ dbih,
               const float* __restrict__ dbhh,
               const float* __restrict__ fc1b, const float* __restrict__ fc2W,
               const float* __restrict__ fc2b, float* __restrict__ out) {
    extern __shared__ float dsm[];
    float* sh_ctx  = dsm + D_CTX;
    float* sh_A    = dsm + D_A;
    float* sh_C    = dsm + D_C;
    float* sh_w    = dsm + D_W;
    float* sh_part = dsm + D_PART;
    float* sh_prev = dsm + D_PREV;
    float* sh_red  = dsm + D_RED;

    const int t = threadIdx.x;
    const int row0 = blockIdx.x * ROWS;
    const int wp = t >> 5, lane = t & 31;
    const int g2 = t >> 8, tj = t & 255;
    const int qg = t >> 7, h2 = t & 127;

    for (int i = t; i < ROWS * TDIM; i += 512) {
        int r = i >> 7, tt = i & 127;
        sh_A[r * TDIM + tt] = g_A[(row0 + r) * TDIM + tt];
        sh_C[r * TDIM + tt] = g_C[(row0 + r) * TDIM + tt];
    }
    if (t < ROWS)
        sh_prev[t] = x[((size_t)(row0 + t) * TDIM + (TDIM - 1)) * FDIM + 0];

    const float dbr  = dbih[tj]          + dbhh[tj];
    const float dbz  = dbih[tj + HDIM]   + dbhh[tj + HDIM];
    const float dbin = dbih[tj + 2*HDIM];
    const float dbhn = dbhh[tj + 2*HDIM];
    const float wir  = dWih[tj], wiz = dWih[tj + HDIM], win = dWih[tj + 2*HDIM];
    const float f1b  = fc1b[tj];
    const float f2w  = fc2W[tj];
    const float f2b  = fc2b[0];
    const float scale = 0.0625f;
    __syncthreads();

    for (int step = 0; step < OUTL; ++step) {
        {
            int r = wp;
            float pv = sh_prev[r];
            float sv[4], m = -1e30f;
            #pragma unroll
            for (int i = 0; i < 4; ++i) {
                int tt = lane + 32 * i;
                float s = (pv * sh_A[r * TDIM + tt] + sh_C[r * TDIM + tt]) * scale;
                sv[i] = s; m = fmaxf(m, s);
            }
            #pragma unroll
            for (int off = 16; off; off >>= 1) m = fmaxf(m, __shfl_xor_sync(0xffffffffu, m, off));
            float sum = 0.f;
            #pragma unroll
            for (int i = 0; i < 4; ++i) { sv[i] = __expf(sv[i] - m); sum += sv[i]; }
            #pragma unroll
            for (int off = 16; off; off >>= 1) sum += __shfl_xor_sync(0xffffffffu, sum, off);
            float inv = __fdividef(1.f, sum);
            #pragma unroll
            for (int i = 0; i < 4; ++i) sh_w[r * TDIM + lane + 32 * i] = sv[i] * inv;
        }
        __syncthreads();

        {
            float a0x = 0.f, a0y = 0.f, a1x = 0.f, a1y = 0.f;
            float a2x = 0.f, a2y = 0.f, a3x = 0.f, a3y = 0.f;
            const __half* hb =
                g_hsh + ((size_t)(row0 + qg * 4) * TDIM) * HDIM + 2 * h2;
            const size_t rstride = (size_t)TDIM * HDIM;
            #pragma unroll 2
            for (int tt = 0; tt < TDIM; ++tt) {
                const __half* hp = hb + (size_t)tt * HDIM;
                __half2 v0 = *reinterpret_cast<const __half2*>(hp);
                __half2 v1 = *reinterpret_cast<const __half2*>(hp + rstride);
                __half2 v2 = *reinterpret_cast<const __half2*>(hp + 2 * rstride);
                __half2 v3 = *reinterpret_cast<const __half2*>(hp + 3 * rstride);
                float w0 = sh_w[(qg * 4 + 0) * TDIM + tt];
                float w1 = sh_w[(qg * 4 + 1) * TDIM + tt];
                float w2 = sh_w[(qg * 4 + 2) * TDIM + tt];
                float w3 = sh_w[(qg * 4 + 3) * TDIM + tt];
                float2 f0 = __half22float2(v0);
                float2 f1 = __half22float2(v1);
                float2 f2 = __half22float2(v2);
                float2 f3 = __half22float2(v3);
                a0x = fmaf(w0, f0.x, a0x); a0y = fmaf(w0, f0.y, a0y);
                a1x = fmaf(w1, f1.x, a1x); a1y = fmaf(w1, f1.y, a1y);
                a2x = fmaf(w2, f2.x, a2x); a2y = fmaf(w2, f2.y, a2y);
                a3x = fmaf(w3, f3.x, a3x); a3y = fmaf(w3, f3.y, a3y);
            }
            int hx = 2 * h2, r0 = qg * 4;
            sh_ctx[hx * PAD + r0 + 0] = a0x; sh_ctx[(hx + 1) * PAD + r0 + 0] = a0y;
            sh_ctx[hx * PAD + r0 + 1] = a1x; sh_ctx[(hx + 1) * PAD + r0 + 1] = a1y;
            sh_ctx[hx * PAD + r0 + 2] = a2x; sh_ctx[(hx + 1) * PAD + r0 + 2] = a2y;
            sh_ctx[hx * PAD + r0 + 3] = a3x; sh_ctx[(hx + 1) * PAD + r0 + 3] = a3y;
        }
        __syncthreads();

        u64 ar[RP], az[RP], ahn[RP], ain[RP];
        if (g2 == 0) {
            #pragma unroll
            for (int rp = 0; rp < RP; ++rp) {
                float p0 = sh_prev[2*rp], p1 = sh_prev[2*rp + 1];
                ar[rp]  = pk2p(fmaf(p0, wir, dbr),  fmaf(p1, wir, dbr));
                az[rp]  = pk2p(fmaf(p0, wiz, dbz),  fmaf(p1, wiz, dbz));
                ain[rp] = pk2p(fmaf(p0, win, dbin), fmaf(p1, win, dbin));
                ahn[rp] = pk2(dbhn);
            }
        } else {
            u64 z0 = pk2(0.f);
            #pragma unroll
            for (int rp = 0; rp < RP; ++rp) { ar[rp]=z0; az[rp]=z0; ahn[rp]=z0; ain[rp]=z0; }
        }
        {
            const int k0 = g2 * 128;
            #pragma unroll 2
            for (int kk = 0; kk < 128; ++kk) {
                int k = k0 + kk;
                float2 w  = g_DWrz[k * 256 + tj];
                float  wn = g_DWn [k * 256 + tj];
                u64 wr = pk2(w.x), wzv = pk2(w.y), wn2 = pk2(wn);
                #pragma unroll
                for (int rp = 0; rp < RP; ++rp) {
                    u64 cv = lds2(&sh_ctx[k * PAD + 2*rp]);
                    fma2(ar[rp],  cv, wr);
                    fma2(az[rp],  cv, wzv);
                    fma2(ahn[rp], cv, wn2);
                }
            }
        }
        if (g2 == 1) {
            float* pp = sh_part + tj * 48;
            #pragma unroll
            for (int rp = 0; rp < RP; ++rp) {
                float2 v = upk(ar[rp]);  pp[2*rp]      = v.x; pp[2*rp + 1]      = v.y;
                float2 w = upk(az[rp]);  pp[16 + 2*rp] = w.x; pp[16 + 2*rp + 1] = w.y;
                float2 h = upk(ahn[rp]); pp[32 + 2*rp] = h.x; pp[32 + 2*rp + 1] = h.y;
            }
        }
        __syncthreads();

        if (g2 == 0) {
            const float* pp = sh_part + tj * 48;
            float hd[ROWS];
            #pragma unroll
            for (int rp = 0; rp < RP; ++rp) {
                float2 vr = upk(ar[rp]);  vr.x += pp[2*rp];      vr.y += pp[2*rp + 1];
                float2 vz = upk(az[rp]);  vz.x += pp[16 + 2*rp]; vz.y += pp[16 + 2*rp + 1];
                float2 vi = upk(ain[rp]);
                float2 vh = upk(ahn[rp]); vh.x += pp[32 + 2*rp]; vh.y += pp[32 + 2*rp + 1];
                float r0 = sigmoidf_(vr.x), r1 = sigmoidf_(vr.y);
                float z0 = sigmoidf_(vz.x), z1 = sigmoidf_(vz.y);
                float n0 = tanhf_(vi.x + r0 * vh.x);
                float n1 = tanhf_(vi.y + r1 * vh.y);
                float c0 = sh_ctx[tj * PAD + 2*rp];
                float c1 = sh_ctx[tj * PAD + 2*rp + 1];
                hd[2*rp]     = (1.f - z0) * n0 + z0 * c0;
                hd[2*rp + 1] = (1.f - z1) * n1 + z1 * c1;
            }
            #pragma unroll
            for (int r = 0; r < ROWS; ++r) sh_ctx[tj * PAD + r] = hd[r];
        }
        __syncthreads();

        u64 a1[RP];
        {
            u64 b1 = (g2 == 0) ? pk2(f1b) : pk2(0.f);
            #pragma unroll
            for (int rp = 0; rp < RP; ++rp) a1[rp] = b1;
            const int k0 = g2 * 128;
            #pragma unroll 2
            for (int kk = 0; kk < 128; ++kk) {
                int k = k0 + kk;
                u64 wf = pk2(g_WtFc1[k * FCH + tj]);
                #pragma unroll
                for (int rp = 0; rp < RP; ++rp) {
                    u64 hv = lds2(&sh_ctx[k * PAD + 2*rp]);
                    fma2(a1[rp], hv, wf);
                }
            }
        }
        if (g2 == 1) {
            float* pp = sh_part + tj * 48;
            #pragma unroll
            for (int rp = 0; rp < RP; ++rp) {
                float2 v = upk(a1[rp]);
                pp[2*rp] = v.x; pp[2*rp + 1] = v.y;
            }
        }
        __syncthreads();

        if (g2 == 0) {
            const float* pp = sh_part + tj * 48;
            float p[ROWS];
            #pragma unroll
            for (int rp = 0; rp < RP; ++rp) {
                float2 v = upk(a1[rp]);
                p[2*rp]     = fmaxf(v.x + pp[2*rp],     0.f) * f2w;
                p[2*rp + 1] = fmaxf(v.y + pp[2*rp + 1], 0.f) * f2w;
            }
            #pragma unroll
            for (int off = 16; off; off >>= 1) {
                #pragma unroll
                for (int r = 0; r < ROWS; ++r)
                    p[r] += __shfl_xor_sync(0xffffffffu, p[r], off);
            }
            if (lane == 0) {
                #pragma unroll
                for (int r = 0; r < ROWS; ++r) sh_red[wp * ROWS + r] = p[r];
            }
        }
        __syncthreads();
        if (t < ROWS) {
            float s = f2b;
            #pragma unroll
            for (int w = 0; w < 8; ++w) s += sh_red[w * ROWS + t];
            out[(size_t)(row0 + t) * OUTL + step] = s;
            sh_prev[t] = s;
        }
        __syncthreads();
    }
}

// ---------------- launch ----------------
extern "C" void kernel_launch(void* const* d_in, const int* in_sizes, int n_in,
                              void* d_out, int out_size) {
    (void)in_sizes; (void)n_in; (void)out_size;
    const float* x       = (const float*)d_in[0];
    const float* h0      = (const float*)d_in[1];
    const float* enc_Wih = (const float*)d_in[2];
    const float* enc_Whh = (const float*)d_in[3];
    const float* enc_bih = (const float*)d_in[4];
    const float* enc_bhh = (const float*)d_in[5];
    const float* dec_Wih = (const float*)d_in[6];
    const float* dec_Whh = (const float*)d_in[7];
    const float* dec_bih = (const float*)d_in[8];
    const float* dec_bhh = (const float*)d_in[9];
    const float* attn_Wq = (const float*)d_in[10];
    const float* attn_bq = (const float*)d_in[11];
    const float* fc1_W   = (const float*)d_in[12];
    const float* fc1_b   = (const float*)d_in[13];
    const float* fc2_W   = (const float*)d_in[14];
    const float* fc2_b   = (const float*)d_in[15];
    float* out = (float*)d_out;

    const int enc_smem = ENC_SMEM_FLOATS * (int)sizeof(float);   // 118784 B
    const int dec_smem = DEC_SMEM_FLOATS * (int)sizeof(float);   // 93248 B
    cudaFuncSetAttribute(encoder_kernel,
                         cudaFuncAttributeMaxDynamicSharedMemorySize, enc_smem);
    cudaFuncSetAttribute(decoder_kernel,
                         cudaFuncAttributeMaxDynamicSharedMemorySize, dec_smem);

    prep_kernel<<<256, 256>>>(enc_Wih, enc_Whh, dec_Whh, fc1_W);
    gi_kernel<<<NCTA * TDIM, NTHR>>>(x);
    encoder_kernel<<<NCTA, 512, enc_smem>>>(h0, enc_bih, enc_bhh, attn_Wq, attn_bq);
    decoder_kernel<<<NCTA, 512, dec_smem>>>(x, dec_Wih, dec_bih, dec_bhh,
                                            fc1_b, fc2_W, fc2_b, out);
}